// round 2
// baseline (speedup 1.0000x reference)
#include <cuda_runtime.h>
#include <stdint.h>

// Problem constants
#define B 64
#define H 256
#define W 256
#define T 1000
#define NROWS (B * H)                 // 16384 rows (b,h)
#define TOTAL_OUT ((double)B * H * T) // 16,384,000 elements in the MSE mean

__global__ void zero_scalar_kernel(float* out) {
    if (threadIdx.x == 0 && blockIdx.x == 0) out[0] = 0.0f;
}

// One block per (b,h) row. 256 threads, one per column w.
// Shared: two 1000-bin int max-histograms (init 0 == jnp zeros base).
__global__ __launch_bounds__(256, 8)
void holo_mse_kernel(const float* __restrict__ rec,
                     const float* __restrict__ tgt,
                     float* __restrict__ out)
{
    __shared__ int binsA[T];
    __shared__ int binsB[T];
    __shared__ float warp_sums[8];

    const int row = blockIdx.x;           // = b*H + h
    const int t   = threadIdx.x;          // = w
    const float* __restrict__ ra = rec + (size_t)row * W;
    const float* __restrict__ rb = tgt + (size_t)row * W;

    // init bins
    #pragma unroll
    for (int i = t; i < T; i += 256) { binsA[i] = 0; binsB[i] = 0; }
    __syncthreads();

    // scatter-max: value is the column index w (= t)
    float xa = ra[t];
    float xb = rb[t];
    if (xa != 0.0f) {
        int q = (int)(xa * 1000.0f) - 1;   // trunc, matches jnp astype(int32)
        if (q < 0) q += T;                 // floor-mod: only -1 -> 999 possible
        atomicMax(&binsA[q], t);
    }
    if (xb != 0.0f) {
        int q = (int)(xb * 1000.0f) - 1;
        if (q < 0) q += T;
        atomicMax(&binsB[q], t);
    }
    __syncthreads();

    // per-row sum of squared differences over the 1000 bins
    float s = 0.0f;
    #pragma unroll
    for (int i = t; i < T; i += 256) {
        float d = (float)(binsA[i] - binsB[i]);
        s += d * d;
    }

    // block reduction (8 warps)
    #pragma unroll
    for (int off = 16; off > 0; off >>= 1)
        s += __shfl_down_sync(0xffffffffu, s, off);
    if ((t & 31) == 0) warp_sums[t >> 5] = s;
    __syncthreads();
    if (t < 32) {
        float v = (t < 8) ? warp_sums[t] : 0.0f;
        #pragma unroll
        for (int off = 4; off > 0; off >>= 1)
            v += __shfl_down_sync(0xffffffffu, v, off);
        if (t == 0) {
            // pre-scale by 1/N so the atomic accumulates the mean directly
            atomicAdd(out, v * (float)(1.0 / TOTAL_OUT));
        }
    }
}

extern "C" void kernel_launch(void* const* d_in, const int* in_sizes, int n_in,
                              void* d_out, int out_size)
{
    const float* rec = (const float*)d_in[0];
    const float* tgt = (const float*)d_in[1];
    float* out = (float*)d_out;

    zero_scalar_kernel<<<1, 32>>>(out);
    holo_mse_kernel<<<NROWS, 256>>>(rec, tgt, out);
}

// round 3
// speedup vs baseline: 1.4863x; 1.4863x over previous
#include <cuda_runtime.h>
#include <stdint.h>

// Problem constants
#define B 64
#define H 256
#define W 256
#define T 1000
#define TPAD 1024                      // padded bin count (pads never written, tag-mismatch -> 0)
#define NROWS (B * H)                  // 16384 rows (b,h)
#define TOTAL_OUT ((double)B * H * T)  // 16,384,000 elements in the MSE mean
#define GRID 1216                      // ~8 blocks per SM on 152-SM GB300

__global__ void zero_scalar_kernel(float* out) {
    if (threadIdx.x == 0 && blockIdx.x == 0) out[0] = 0.0f;
}

// Persistent blocks. Each block walks rows with stride GRID.
// Bins hold (iter << 8) | w  -- monotone tag means no re-init is ever needed:
// stale entries (smaller iter) lose every atomicMax against current-iter
// entries, and decode to 0 on tag mismatch (== the jnp zeros base; note a
// genuine hit with w=0 also contributes 0, so the encodings coincide).
// Double-buffered so a single __syncthreads per row suffices.
__global__ __launch_bounds__(256, 8)
void holo_mse_kernel(const float* __restrict__ rec,
                     const float* __restrict__ tgt,
                     float* __restrict__ out)
{
    __shared__ int2 bins[2][TPAD];     // .x = rec histogram, .y = tgt histogram (16 KB)
    __shared__ float warp_sums[8];

    const int t = threadIdx.x;         // = column w

    // one-time zero init (tag 0; iter starts at 1 so it never matches)
    #pragma unroll
    for (int i = t; i < TPAD; i += 256) {
        bins[0][i] = make_int2(0, 0);
        bins[1][i] = make_int2(0, 0);
    }
    __syncthreads();

    float acc = 0.0f;
    int iter = 1;

    for (int row = blockIdx.x; row < NROWS; row += GRID, ++iter) {
        const int p = iter & 1;
        const float xa = rec[(size_t)row * W + t];
        const float xb = tgt[(size_t)row * W + t];
        const int tagw = (iter << 8) | t;

        if (xa != 0.0f) {
            int q = (int)(xa * 1000.0f) - 1;   // trunc == jnp astype(int32)
            if (q < 0) q += T;                 // floor-mod: only -1 -> 999 possible
            atomicMax(&bins[p][q].x, tagw);
        }
        if (xb != 0.0f) {
            int q = (int)(xb * 1000.0f) - 1;
            if (q < 0) q += T;
            atomicMax(&bins[p][q].y, tagw);
        }
        __syncthreads();                       // atomics done before reads; also
                                               // orders prior reads before buffer reuse

        const int hi = iter << 8;
        int srow = 0;
        #pragma unroll
        for (int i = t; i < TPAD; i += 256) {
            int2 v = bins[p][i];
            int a = ((v.x & ~255) == hi) ? (v.x & 255) : 0;
            int b = ((v.y & ~255) == hi) ? (v.y & 255) : 0;
            int d = a - b;
            srow += d * d;                     // <= 1000 * 255^2, fits int easily
        }
        acc += (float)srow;                    // per-thread per-row partial is exact in fp32
    }

    // single block reduction at the end
    #pragma unroll
    for (int off = 16; off > 0; off >>= 1)
        acc += __shfl_down_sync(0xffffffffu, acc, off);
    if ((t & 31) == 0) warp_sums[t >> 5] = acc;
    __syncthreads();
    if (t < 32) {
        float v = (t < 8) ? warp_sums[t] : 0.0f;
        #pragma unroll
        for (int off = 4; off > 0; off >>= 1)
            v += __shfl_down_sync(0xffffffffu, v, off);
        if (t == 0)
            atomicAdd(out, v * (float)(1.0 / TOTAL_OUT));
    }
}

extern "C" void kernel_launch(void* const* d_in, const int* in_sizes, int n_in,
                              void* d_out, int out_size)
{
    const float* rec = (const float*)d_in[0];
    const float* tgt = (const float*)d_in[1];
    float* out = (float*)d_out;

    zero_scalar_kernel<<<1, 32>>>(out);
    holo_mse_kernel<<<GRID, 256>>>(rec, tgt, out);
}

// round 6
// speedup vs baseline: 1.6497x; 1.1100x over previous
#include <cuda_runtime.h>
#include <stdint.h>

// Problem constants
#define B 64
#define H 256
#define W 256
#define T 1000
#define TPAD 1024                      // alignment padding only (bins never scanned now)
#define NROWS (B * H)                  // 16384 rows (b,h)
#define TOTAL_OUT ((double)B * H * T)  // 16,384,000 elements in the MSE mean
#define GRID 1216                      // 8 blocks per SM on 152-SM GB300

__global__ void zero_scalar_kernel(float* out) {
    if (threadIdx.x == 0 && blockIdx.x == 0) out[0] = 0.0f;
}

__device__ __forceinline__ int quantize(float x) {
    int q = (int)(x * 1000.0f) - 1;    // trunc == jnp astype(int32)
    if (q < 0) q += T;                 // floor-mod: only -1 -> 999 possible
    return q;
}

// Persistent blocks, tagged bins ((iter<<8)|w  -- monotone, so no re-init),
// double-buffered with ONE barrier per row.
//
// Sparse ownership reduction: tags are unique per (thread,iter), so after the
// barrier each thread re-reads only the bin(s) IT wrote. If its tag won the
// atomicMax it "owns" that bin and contributes that bin's (a-b)^2 term:
//   A-owner of bin q:  (a - b_q)^2   (b_q decoded from the paired .y word)
//   B-owner of bin q:  b^2           but only if A has no current-iter entry
// Every nonzero bin counted exactly once; zero bins contribute 0. No scan.
__global__ __launch_bounds__(256, 8)
void holo_mse_kernel(const float* __restrict__ rec,
                     const float* __restrict__ tgt,
                     float* __restrict__ out)
{
    __shared__ int2 bins[2][TPAD];     // .x = rec histogram, .y = tgt histogram (16 KB)
    __shared__ float warp_sums[8];

    const int t = threadIdx.x;         // = column w

    // one-time zero init (tag 0; iter starts at 1 so it never matches)
    #pragma unroll
    for (int i = t; i < TPAD; i += 256) {
        bins[0][i] = make_int2(0, 0);
        bins[1][i] = make_int2(0, 0);
    }
    __syncthreads();

    float acc = 0.0f;
    int iter = 1;

    // preload first row
    int row = blockIdx.x;
    float xa = rec[(size_t)row * W + t];
    float xb = tgt[(size_t)row * W + t];

    for (; row < NROWS; row += GRID, ++iter) {
        const int p    = iter & 1;
        const int hi   = iter << 8;
        const int tagw = hi | t;

        int qa = -1, qb = -1;
        if (xa != 0.0f) { qa = quantize(xa); atomicMax(&bins[p][qa].x, tagw); }
        if (xb != 0.0f) { qb = quantize(xb); atomicMax(&bins[p][qb].y, tagw); }

        // prefetch next row's inputs (hidden behind barrier + ownership phase)
        const int nrow = row + GRID;
        if (nrow < NROWS) {
            xa = rec[(size_t)nrow * W + t];
            xb = tgt[(size_t)nrow * W + t];
        }

        __syncthreads();               // atomics visible; also fences buffer reuse

        int srow = 0;
        if (qa >= 0) {
            int2 v = bins[p][qa];
            if (v.x == tagw) {                                   // I own A-bin qa
                int b = ((v.y & ~255) == hi) ? (v.y & 255) : 0;  // paired B value
                int d = t - b;
                srow += d * d;
            }
        }
        if (qb >= 0) {
            int2 v = bins[p][qb];
            if (v.y == tagw && (v.x & ~255) != hi)               // I own B-bin qb, A empty there
                srow += t * t;
        }
        acc += (float)srow;
    }

    // single block reduction at the end
    #pragma unroll
    for (int off = 16; off > 0; off >>= 1)
        acc += __shfl_down_sync(0xffffffffu, acc, off);
    if ((t & 31) == 0) warp_sums[t >> 5] = acc;
    __syncthreads();
    if (t < 32) {
        float v = (t < 8) ? warp_sums[t] : 0.0f;
        #pragma unroll
        for (int off = 4; off > 0; off >>= 1)
            v += __shfl_down_sync(0xffffffffu, v, off);
        if (t == 0)
            atomicAdd(out, v * (float)(1.0 / TOTAL_OUT));
    }
}

extern "C" void kernel_launch(void* const* d_in, const int* in_sizes, int n_in,
                              void* d_out, int out_size)
{
    const float* rec = (const float*)d_in[0];
    const float* tgt = (const float*)d_in[1];
    float* out = (float*)d_out;

    zero_scalar_kernel<<<1, 32>>>(out);
    holo_mse_kernel<<<GRID, 256>>>(rec, tgt, out);
}

// round 7
// speedup vs baseline: 1.8190x; 1.1026x over previous
#include <cuda_runtime.h>
#include <stdint.h>

// Problem constants
#define B 64
#define H 256
#define W 256
#define T 1000
#define TPAD 1024                      // alignment padding only
#define NROWS (B * H)                  // 16384 rows (b,h)
#define TOTAL_OUT ((double)B * H * T)  // 16,384,000 elements in the MSE mean
#define GRID 1216                      // 8 blocks per SM on 152-SM GB300

__global__ void zero_scalar_kernel(float* out) {
    if (threadIdx.x == 0 && blockIdx.x == 0) out[0] = 0.0f;
}

__device__ __forceinline__ int quantize(float x) {
    int q = (int)(x * 1000.0f) - 1;    // trunc == jnp astype(int32)
    if (q < 0) q += T;                 // floor-mod: only -1 -> 999 possible
    return q;
}

// Persistent blocks, tagged bins ((iter<<8)|w -- monotone, so no re-init),
// double-buffered, ONE barrier per row.
//
// Sum decomposition:  sum_q (a_q - b_q)^2 = sum a_q^2 + sum b_q^2 - 2 sum a_q*b_q
//  * squared terms: telescoping from atomicMax RETURN values. Atomics at a bin
//    serialize; each overtaking thread adds (t^2 - prev_w^2), where a
//    stale-tag prev decodes to 0. Sum over the serialized chain = final_max^2.
//    -> NO post-barrier re-read needed for either histogram's squares.
//  * cross term: after the barrier, the A-winner of bin q (v.x == its tag)
//    does ONE LDS.64 and contributes -2 * t * b_q (b_q decoded from v.y).
//    Bins without a current A entry have a_q = 0 -> cross term 0, nobody
//    needs to compute it.
__global__ __launch_bounds__(256, 8)
void holo_mse_kernel(const float* __restrict__ rec,
                     const float* __restrict__ tgt,
                     float* __restrict__ out)
{
    __shared__ int2 bins[2][TPAD];     // .x = rec histogram, .y = tgt histogram (16 KB)
    __shared__ float warp_sums[8];

    const int t   = threadIdx.x;       // = column w
    const int tsq = t * t;

    // one-time zero init (tag 0; iter starts at 1 so it never matches)
    #pragma unroll
    for (int i = t; i < TPAD; i += 256) {
        bins[0][i] = make_int2(0, 0);
        bins[1][i] = make_int2(0, 0);
    }
    __syncthreads();

    float acc = 0.0f;
    int iter = 1;

    // preload first row
    int row = blockIdx.x;
    float xa = rec[(size_t)row * W + t];
    float xb = tgt[(size_t)row * W + t];

    for (; row < NROWS; row += GRID, ++iter) {
        const int p    = iter & 1;
        const int hi   = iter << 8;
        const int tagw = hi | t;

        int srow = 0;
        int qa = -1;
        if (xa != 0.0f) {
            qa = quantize(xa);
            int old = atomicMax(&bins[p][qa].x, tagw);
            if (tagw > old) {                          // we overtook prev
                unsigned pw = (unsigned)(old - hi);    // current-iter iff < 256
                int pv = (pw < 256u) ? (int)pw : 0;
                srow += tsq - pv * pv;
            }
        }
        if (xb != 0.0f) {
            int qb = quantize(xb);
            int old = atomicMax(&bins[p][qb].y, tagw);
            if (tagw > old) {
                unsigned pw = (unsigned)(old - hi);
                int pv = (pw < 256u) ? (int)pw : 0;
                srow += tsq - pv * pv;
            }
        }

        // prefetch next row's inputs (hidden behind barrier + cross-term phase)
        const int nrow = row + GRID;
        if (nrow < NROWS) {
            xa = rec[(size_t)nrow * W + t];
            xb = tgt[(size_t)nrow * W + t];
        }

        __syncthreads();               // atomics visible; also fences buffer reuse

        // cross term: A-winner reads the pair once
        if (qa >= 0) {
            int2 v = bins[p][qa];
            if (v.x == tagw) {
                unsigned db = (unsigned)(v.y - hi);
                int b = (db < 256u) ? (int)db : 0;
                srow -= 2 * t * b;
            }
        }
        acc += (float)srow;            // |srow| < 2^19, <=14 rows: fp32-exact
    }

    // single block reduction at the end
    #pragma unroll
    for (int off = 16; off > 0; off >>= 1)
        acc += __shfl_down_sync(0xffffffffu, acc, off);
    if ((t & 31) == 0) warp_sums[t >> 5] = acc;
    __syncthreads();
    if (t < 32) {
        float v = (t < 8) ? warp_sums[t] : 0.0f;
        #pragma unroll
        for (int off = 4; off > 0; off >>= 1)
            v += __shfl_down_sync(0xffffffffu, v, off);
        if (t == 0)
            atomicAdd(out, v * (float)(1.0 / TOTAL_OUT));
    }
}

extern "C" void kernel_launch(void* const* d_in, const int* in_sizes, int n_in,
                              void* d_out, int out_size)
{
    const float* rec = (const float*)d_in[0];
    const float* tgt = (const float*)d_in[1];
    float* out = (float*)d_out;

    zero_scalar_kernel<<<1, 32>>>(out);
    holo_mse_kernel<<<GRID, 256>>>(rec, tgt, out);
}